// round 10
// baseline (speedup 1.0000x reference)
#include <cuda_runtime.h>
#include <math.h>
#include <stdint.h>

typedef unsigned long long ull;

#define B 64
#define H 1024
#define HY 256
#define F 64
#define IND 133
#define NSEQ 128
#define OUTD 123
#define GRID 148

// ---------------- persistent device state ----------------------------------
__device__ __align__(16) float g_h[H][B];
__device__ __align__(16) float g_c[H][B];
__device__ __align__(16) float g_hh[2][HY][B];
__device__ __align__(16) float g_ch[HY][B];
__device__ __align__(16) float g_ahp[4][4 * H][B];      // h@Wh split-K partials
__device__ __align__(16) float g_x[NSEQ][IND][B];
__device__ __align__(16) float g_axp[NSEQ][4 * H][B];   // precomputed x@Wx
__device__ __align__(16) float g_gxh[NSEQ][4 * HY][B];  // precomputed x@Wxh(x-rows)
__device__ __align__(16) float g_E[3][HY][4 * H];       // fused Wz@D (12.6MB)
__device__ __align__(16) float g_Ebias[2][4 * H];       // bz@D (zb has no bias)
__device__ __align__(16) float g_outs[NSEQ][H][B];
__device__ __align__(16) float g_dec[NSEQ][OUTD][B];
__device__ unsigned g_bar_count;
__device__ unsigned g_bar_gen;

__device__ __forceinline__ float sigf(float x) { return 1.0f / (1.0f + expf(-x)); }

__device__ __forceinline__ void fma2(ull& d, ull a, ull b) {
    asm("fma.rn.f32x2 %0, %1, %2, %0;" : "+l"(d) : "l"(a), "l"(b));
}
__device__ __forceinline__ ull mul2(ull a, ull b) {
    ull d; asm("mul.rn.f32x2 %0, %1, %2;" : "=l"(d) : "l"(a), "l"(b)); return d;
}
__device__ __forceinline__ ull add2(ull a, ull b) {
    ull d; asm("add.rn.f32x2 %0, %1, %2;" : "=l"(d) : "l"(a), "l"(b)); return d;
}
__device__ __forceinline__ ull pack2(float x, float y) {
    ull r; asm("mov.b64 %0, {%1, %2};" : "=l"(r) : "f"(x), "f"(y)); return r;
}

// ---------------- cp.async helpers ------------------------------------------
__device__ __forceinline__ void cpa16(void* dst, const void* src) {
    unsigned d = (unsigned)__cvta_generic_to_shared(dst);
    asm volatile("cp.async.cg.shared.global [%0], [%1], 16;" :: "r"(d), "l"(src));
}
__device__ __forceinline__ void cpa_commit() {
    asm volatile("cp.async.commit_group;");
}
template<int N>
__device__ __forceinline__ void cpa_wait() {
    asm volatile("cp.async.wait_group %0;" :: "n"(N));
}

// ---------------- grid-wide barrier (all blocks co-resident) ----------------
__device__ __forceinline__ void grid_bar() {
    __syncthreads();
    if (threadIdx.x == 0) {
        unsigned gen = *(volatile unsigned*)&g_bar_gen;
        __threadfence();
        unsigned arr = atomicAdd(&g_bar_count, 1u);
        if (arr == GRID - 1) {
            *(volatile unsigned*)&g_bar_count = 0u;
            __threadfence();
            *(volatile unsigned*)&g_bar_gen = gen + 1u;
        } else {
            while (*(volatile unsigned*)&g_bar_gen == gen) {}
        }
        __threadfence();
    }
    __syncthreads();
}

// ---------------- 3-stage cp.async 32-col GEMM core --------------------------
// acc[4] (+=): 32 cols x 64 batch; thread = 4 cols (cg4) x 2 batch (bg2).
// GS=0: contiguous cols [cb,cb+32). GS>0: 4 groups of 8 cols, group g at
// W col g*GS + cb + (0..7).  K = 32*nst.
// smem: sA = sm[0..6144) (3x2048), sW = sm[6144..9216) (3x1024).
template<int GS>
__device__ __forceinline__ void mm32(const float* __restrict__ A,
                                     const float* __restrict__ W,
                                     int ldw, int cb, int nst,
                                     float* sm, ull (&acc)[4], int tid) {
    float* sA = sm;
    float* sW = sm + 6144;
    const int ar  = tid >> 4;
    const int ac4 = (tid & 15) << 2;
    const int wr  = tid >> 3;
    const int wq  = tid & 7;
    const int cg4 = (tid >> 5) << 2;
    const int bg2 = (tid & 31) << 1;

#define MM32_LOAD(s) do {                                                     \
        int _stg = (s) % 3;                                                   \
        int _k0 = (s) << 5;                                                   \
        float* _dA = sA + _stg * 2048;                                        \
        float* _dW = sW + _stg * 1024;                                        \
        cpa16(_dA + ar * 64 + ac4, A + (_k0 + ar) * 64 + ac4);                \
        cpa16(_dA + (ar + 16) * 64 + ac4, A + (_k0 + ar + 16) * 64 + ac4);    \
        const float* _ws = GS                                                 \
            ? (W + (_k0 + wr) * ldw + (wq >> 1) * GS + cb + ((wq & 1) << 2))  \
            : (W + (_k0 + wr) * ldw + cb + (wq << 2));                        \
        cpa16(_dW + wr * 32 + (wq << 2), _ws);                                \
        cpa_commit();                                                         \
    } while (0)

    MM32_LOAD(0);
    if (nst > 1) MM32_LOAD(1);
    for (int s = 0; s < nst; s++) {
        if (s + 1 < nst) cpa_wait<1>(); else cpa_wait<0>();
        __syncthreads();
        int stg = s % 3;
        const float* cA = sA + stg * 2048;
        const float* cW = sW + stg * 1024;
#pragma unroll
        for (int k = 0; k < 32; k++) {
            ull a = *(const ull*)(cA + k * 64 + bg2);
            float4 w = *(const float4*)(cW + k * 32 + cg4);
            fma2(acc[0], a, pack2(w.x, w.x));
            fma2(acc[1], a, pack2(w.y, w.y));
            fma2(acc[2], a, pack2(w.z, w.z));
            fma2(acc[3], a, pack2(w.w, w.w));
        }
        __syncthreads();
        if (s + 2 < nst) MM32_LOAD(s + 2);
    }
#undef MM32_LOAD
}

// ---------------- prologue kernels ------------------------------------------
__device__ __forceinline__ void gemm_seg64(const float* __restrict__ A,
                                           const float* __restrict__ W,
                                           int K, int ldw, int colbase,
                                           float (*sA)[64], float (*sW)[64],
                                           ull (&acc)[4][2], int tid) {
    const int row = tid >> 4;
    const int q4  = (tid & 15) << 2;
    const int bg4 = (tid & 15) << 2;
    const int cg4 = (tid >> 4) << 2;
    const int nst = (K + 15) >> 4;
    const float4 f40 = make_float4(0.f, 0.f, 0.f, 0.f);

    float4 pa = (row < K) ? *(const float4*)(A + row * 64 + q4) : f40;
    float4 pw = (row < K) ? *(const float4*)(W + row * ldw + colbase + q4) : f40;

    for (int s = 0; s < nst; s++) {
        __syncthreads();
        *(float4*)(&sA[row][q4]) = pa;
        *(float4*)(&sW[row][q4]) = pw;
        __syncthreads();
        if (s + 1 < nst) {
            int kn = (s + 1) * 16 + row;
            pa = (kn < K) ? *(const float4*)(A + kn * 64 + q4) : f40;
            pw = (kn < K) ? *(const float4*)(W + kn * ldw + colbase + q4) : f40;
        }
#pragma unroll
        for (int k = 0; k < 16; k++) {
            ulonglong2 a = *(const ulonglong2*)(&sA[k][bg4]);
            float4 w = *(const float4*)(&sW[k][cg4]);
            ull w0 = pack2(w.x, w.x), w1 = pack2(w.y, w.y);
            ull w2 = pack2(w.z, w.z), w3 = pack2(w.w, w.w);
            fma2(acc[0][0], a.x, w0); fma2(acc[0][1], a.y, w0);
            fma2(acc[1][0], a.x, w1); fma2(acc[1][1], a.y, w1);
            fma2(acc[2][0], a.x, w2); fma2(acc[2][1], a.y, w2);
            fma2(acc[3][0], a.x, w3); fma2(acc[3][1], a.y, w3);
        }
    }
    __syncthreads();
}

__global__ void k_transpose(const float* __restrict__ strokes) {
    int idx = blockIdx.x * blockDim.x + threadIdx.x;
    if (idx >= NSEQ * B * IND) return;
    int t = idx / (B * IND);
    int r = idx - t * (B * IND);
    int b = r / IND;
    int k = r - b * IND;
    g_x[t][k][b] = strokes[idx];
}

__global__ void k_init(const float* __restrict__ z, const float* __restrict__ w,
                       const float* __restrict__ bias) {
    int idx = blockIdx.x * blockDim.x + threadIdx.x;
    int b = idx & 63;
    int col = idx >> 6;
    if (col >= 2560) return;
    float acc = bias[col];
#pragma unroll 4
    for (int k = 0; k < 128; k++) acc += z[b * 128 + k] * w[k * 2560 + col];
    float v = tanhf(acc);
    if (col < 1024)       g_h[col][b] = v;
    else if (col < 2048)  g_c[col - 1024][b] = v;
    else if (col < 2304)  g_hh[0][col - 2048][b] = v;
    else                  g_ch[col - 2304][b] = v;
}

__global__ void __launch_bounds__(256) k_pre_ax(const float* __restrict__ Wx) {
    __shared__ __align__(16) float sm[2048];
    int t = blockIdx.y, cb = blockIdx.x * 64, tid = threadIdx.x;
    ull acc[4][2] = {};
    gemm_seg64(&g_x[t][0][0], Wx, IND, 4096, cb,
               (float(*)[64])sm, (float(*)[64])(sm + 1024), acc, tid);
    int bg4 = (tid & 15) << 2, cg4 = (tid >> 4) << 2;
#pragma unroll
    for (int c = 0; c < 4; c++) {
        ulonglong2 v; v.x = acc[c][0]; v.y = acc[c][1];
        *(ulonglong2*)(&g_axp[t][cb + cg4 + c][bg4]) = v;
    }
}

__global__ void __launch_bounds__(256) k_pre_gxh(const float* __restrict__ Wxh) {
    __shared__ __align__(16) float sm[2048];
    int t = blockIdx.y, cb = blockIdx.x * 64, tid = threadIdx.x;
    ull acc[4][2] = {};
    gemm_seg64(&g_x[t][0][0], Wxh, IND, 1024, cb,
               (float(*)[64])sm, (float(*)[64])(sm + 1024), acc, tid);
    int bg4 = (tid & 15) << 2, cg4 = (tid >> 4) << 2;
#pragma unroll
    for (int c = 0; c < 4; c++) {
        ulonglong2 v; v.x = acc[c][0]; v.y = acc[c][1];
        *(ulonglong2*)(&g_gxh[t][cb + cg4 + c][bg4]) = v;
    }
}

// E[ty][k][g*1024+j] = sum_f Wz[ty][k][g*64+f] * D[ty][g][f][j]
__global__ void __launch_bounds__(256) k_pre_E(
        const float* __restrict__ Wzx, const float* __restrict__ Wzh,
        const float* __restrict__ Wzb,
        const float* __restrict__ Dx, const float* __restrict__ Dh,
        const float* __restrict__ Db) {
    int ty = blockIdx.z, k = blockIdx.y;
    int g = blockIdx.x >> 2, jc = (blockIdx.x & 3) << 8;
    const float* Wz = (ty == 0) ? Wzx : (ty == 1) ? Wzh : Wzb;
    const float* D  = (ty == 0) ? Dx  : (ty == 1) ? Dh  : Db;
    __shared__ float sw[64];
    if (threadIdx.x < 64) sw[threadIdx.x] = Wz[k * 256 + g * 64 + threadIdx.x];
    __syncthreads();
    int j = jc + threadIdx.x;
    float acc = 0.f;
#pragma unroll 16
    for (int f = 0; f < 64; f++) acc += sw[f] * D[(g * 64 + f) * 1024 + j];
    g_E[ty][k][g * 1024 + j] = acc;
}

// Ebias[ty][g*1024+j] = sum_f bz[ty][g*64+f] * D[ty][g][f][j]   (ty: 0=x,1=h)
__global__ void k_pre_Eb(const float* __restrict__ bzx, const float* __restrict__ bzh,
                         const float* __restrict__ Dx, const float* __restrict__ Dh) {
    int idx = blockIdx.x * 256 + threadIdx.x;
    if (idx >= 8192) return;
    int ty = idx >> 12, col = idx & 4095;
    int g = col >> 10, j = col & 1023;
    const float* bb = ty ? bzh : bzx;
    const float* D  = ty ? Dh  : Dx;
    float acc = 0.f;
#pragma unroll 16
    for (int f = 0; f < 64; f++) acc += bb[g * 64 + f] * D[(g * 64 + f) * 1024 + j];
    g_Ebias[ty][col] = acc;
}

// ---------------- THE persistent recurrence kernel (2 phases/step) ----------
__global__ void __launch_bounds__(256, 1) k_seq(
        const float* __restrict__ Wxh, const float* __restrict__ Whh,
        const float* __restrict__ bhy, const float* __restrict__ Wh,
        const float* __restrict__ b0) {
    // smem: mm32 uses [0,9216); sPre at [9216,11264) -> 44KB
    __shared__ __align__(16) float sm[11264];
    const int bx = blockIdx.x;
    const int tid = threadIdx.x;
    const float* WxhH = Wxh + IND * 1024;

    const int cg4 = (tid >> 5) << 2;
    const int bg2 = (tid & 31) << 1;

    for (int t = 0; t < NSEQ; t++) {
        const int cur = t & 1, nxt = cur ^ 1;

        // ===== P1: hyper gates + hyper cell (32 blocks) || h@Wh (116 blocks) =
        if (bx < 32) {
            const int jbase = bx * 8;
            ull acc[4];
#pragma unroll
            for (int i = 0; i < 4; i++) {
                int c = cg4 + i;
                acc[i] = *(const ull*)(&g_gxh[t][((c >> 3) << 8) + jbase + (c & 7)][bg2]);
            }
            mm32<256>(&g_h[0][0],       WxhH, 1024, jbase, 32, sm, acc, tid);
            mm32<256>(&g_hh[cur][0][0], Whh,  1024, jbase, 8,  sm, acc, tid);

            float* sPre = sm;  // free after mm32
#pragma unroll
            for (int i = 0; i < 4; i++) {
                int c = cg4 + i;
                float bv = bhy[((c >> 3) << 8) + jbase + (c & 7)];
                *(ull*)(&sPre[c * 64 + bg2]) = add2(acc[i], pack2(bv, bv));
            }
            __syncthreads();
#pragma unroll
            for (int r = 0; r < 2; r++) {
                int idx = tid + (r << 8);
                int jl = idx >> 6, b = idx & 63;
                int jg = jbase + jl;
                float iv = sPre[jl * 64 + b];
                float fv = sPre[(8 + jl) * 64 + b];
                float gv = sPre[(16 + jl) * 64 + b];
                float ov = sPre[(24 + jl) * 64 + b];
                float chv = sigf(fv) * g_ch[jg][b] + sigf(iv) * tanhf(gv);
                g_ch[jg][b] = chv;
                g_hh[nxt][jg][b] = sigf(ov) * tanhf(chv);
            }
        } else {
            // h @ Wh : 512 units of (32 cols, K=256). 48 blocks x5, 68 blocks x4.
            int w0 = bx - 32;
            int start = (w0 < 48) ? w0 * 5 : 240 + (w0 - 48) * 4;
            int cnt = (w0 < 48) ? 5 : 4;
            for (int i = 0; i < cnt; i++) {
                int u = start + i;
                int ct = u >> 2, ks = u & 3;
                ull acc[4] = {};
                mm32<0>(&g_h[ks * 256][0], Wh + ks * 256 * 4096, 4096,
                        ct * 32, 8, sm, acc, tid);
#pragma unroll
                for (int c = 0; c < 4; c++)
                    *(ull*)(&g_ahp[ks][ct * 32 + cg4 + c][bg2]) = acc[c];
            }
        }
        grid_bar();

        // ===== P2: sx/sh/sb = hh@E + Eb, combine, main cell (128 blocks) =====
        if (bx < 128) {
            const int jb = bx;  // j in [jb*8, jb*8+8)
            ull aX[4] = {}, aH[4] = {}, aB[4] = {};
            mm32<1024>(&g_hh[nxt][0][0], &g_E[0][0][0], 4096, jb * 8, 8, sm, aX, tid);
            mm32<1024>(&g_hh[nxt][0][0], &g_E[1][0][0], 4096, jb * 8, 8, sm, aH, tid);
            mm32<1024>(&g_hh[nxt][0][0], &g_E[2][0][0], 4096, jb * 8, 8, sm, aB, tid);

            float* sPre = sm + 9216;  // 2048 floats: [32 cols][64 batch]
#pragma unroll
            for (int i = 0; i < 4; i++) {
                int c = cg4 + i;                 // local col: g*8 + jl
                int g = c >> 3, jl = c & 7;
                int col = g * 1024 + jb * 8 + jl;  // global gate-col
                ull ax = *(const ull*)(&g_axp[t][col][bg2]);
                ull h0 = *(const ull*)(&g_ahp[0][col][bg2]);
                ull h1 = *(const ull*)(&g_ahp[1][col][bg2]);
                ull h2 = *(const ull*)(&g_ahp[2][col][bg2]);
                ull h3 = *(const ull*)(&g_ahp[3][col][bg2]);
                ull ah = add2(add2(h0, h1), add2(h2, h3));
                float ebx = g_Ebias[0][col];
                float ebh = g_Ebias[1][col];
                float b0v = b0[col];
                ull sxv = add2(aX[i], pack2(ebx, ebx));
                ull shv = add2(aH[i], pack2(ebh, ebh));
                ull p = mul2(sxv, ax);
                fma2(p, shv, ah);
                p = add2(p, aB[i]);
                p = add2(p, pack2(b0v, b0v));
                *(ull*)(&sPre[c * 64 + bg2]) = p;
            }
            __syncthreads();

#pragma unroll
            for (int r = 0; r < 2; r++) {
                int idx = tid + (r << 8);
                int jl = idx >> 6, b = idx & 63;
                int jg = jb * 8 + jl;
                float iv = sPre[(0 * 8 + jl) * 64 + b];
                float fv = sPre[(1 * 8 + jl) * 64 + b];
                float gv = sPre[(2 * 8 + jl) * 64 + b];
                float ov = sPre[(3 * 8 + jl) * 64 + b];
                float cv = sigf(fv) * g_c[jg][b] + sigf(iv) * tanhf(gv);
                g_c[jg][b] = cv;
                float hn = sigf(ov) * tanhf(cv);
                g_h[jg][b] = hn;
                g_outs[t][jg][b] = hn;
            }
        }
        grid_bar();
    }
}

// ---------------- epilogue ---------------------------------------------------
__global__ void __launch_bounds__(256) k_proj(const float* __restrict__ Wp,
                                              const float* __restrict__ bp) {
    __shared__ __align__(16) float smem[2048];
    float (*sA)[64] = (float(*)[64])smem;
    float (*sW)[64] = (float(*)[64])(smem + 1024);
    int t = blockIdx.y;
    int cb = blockIdx.x * 64;
    int tid = threadIdx.x;
    const float* A = &g_outs[t][0][0];
    const int row = tid >> 4;
    const int q4 = (tid & 15) << 2;
    const int bg4 = (tid & 15) << 2;
    const int cg4 = (tid >> 4) << 2;
    ull acc[4][2] = {};

    float4 pa = *(const float4*)(A + row * 64 + q4);
    float4 pw;
    {
        const float* wr = Wp + row * OUTD + cb + q4;
        pw.x = (cb + q4 + 0 < OUTD) ? wr[0] : 0.f;
        pw.y = (cb + q4 + 1 < OUTD) ? wr[1] : 0.f;
        pw.z = (cb + q4 + 2 < OUTD) ? wr[2] : 0.f;
        pw.w = (cb + q4 + 3 < OUTD) ? wr[3] : 0.f;
    }
    for (int s = 0; s < 64; s++) {
        __syncthreads();
        *(float4*)(&sA[row][q4]) = pa;
        *(float4*)(&sW[row][q4]) = pw;
        __syncthreads();
        if (s + 1 < 64) {
            int kn = (s + 1) * 16 + row;
            pa = *(const float4*)(A + kn * 64 + q4);
            const float* wr = Wp + kn * OUTD + cb + q4;
            pw.x = (cb + q4 + 0 < OUTD) ? wr[0] : 0.f;
            pw.y = (cb + q4 + 1 < OUTD) ? wr[1] : 0.f;
            pw.z = (cb + q4 + 2 < OUTD) ? wr[2] : 0.f;
            pw.w = (cb + q4 + 3 < OUTD) ? wr[3] : 0.f;
        }
#pragma unroll
        for (int k = 0; k < 16; k++) {
            ulonglong2 a = *(const ulonglong2*)(&sA[k][bg4]);
            float4 w = *(const float4*)(&sW[k][cg4]);
            ull w0 = pack2(w.x, w.x), w1 = pack2(w.y, w.y);
            ull w2 = pack2(w.z, w.z), w3 = pack2(w.w, w.w);
            fma2(acc[0][0], a.x, w0); fma2(acc[0][1], a.y, w0);
            fma2(acc[1][0], a.x, w1); fma2(acc[1][1], a.y, w1);
            fma2(acc[2][0], a.x, w2); fma2(acc[2][1], a.y, w2);
            fma2(acc[3][0], a.x, w3); fma2(acc[3][1], a.y, w3);
        }
    }
#pragma unroll
    for (int c = 0; c < 4; c++) {
        int col = cb + cg4 + c;
        if (col < OUTD) {
            float bv = bp[col];
            ull bpp = pack2(bv, bv);
            ulonglong2 v;
            v.x = add2(acc[c][0], bpp);
            v.y = add2(acc[c][1], bpp);
            *(ulonglong2*)(&g_dec[t][col][bg4]) = v;
        }
    }
}

__global__ void k_mdn(float* __restrict__ out) {
    int idx = blockIdx.x * blockDim.x + threadIdx.x;
    if (idx >= NSEQ * B * 21) return;
    int u = idx % 21;
    int r = idx / 21;
    int b = r & 63;
    int t = r >> 6;
    if (u < 20) {
        int m = u;
        int off = t * 20 * 64 + m * 64 + b;
        out[off] = 1.0f;
        out[163840 + off] = g_dec[t][6 * m + 1][b];
        out[327680 + off] = g_dec[t][6 * m + 2][b];
        out[491520 + off] = expf(g_dec[t][6 * m + 3][b]);
        out[655360 + off] = expf(g_dec[t][6 * m + 4][b]);
        out[819200 + off] = tanhf(g_dec[t][6 * m + 5][b]);
    } else {
        float p0 = g_dec[t][120][b], p1 = g_dec[t][121][b], p2 = g_dec[t][122][b];
        float mx = fmaxf(p0, fmaxf(p1, p2));
        float e0 = expf(p0 - mx), e1 = expf(p1 - mx), e2 = expf(p2 - mx);
        float s = e0 + e1 + e2;
        int base = 983040 + t * (B * 3) + b * 3;
        out[base + 0] = e0 / s;
        out[base + 1] = e1 / s;
        out[base + 2] = e2 / s;
    }
}

// ---------------- host driver ------------------------------------------------
extern "C" void kernel_launch(void* const* d_in, const int* in_sizes, int n_in,
                              void* d_out, int out_size) {
    const float* z        = (const float*)d_in[0];
    const float* strokes  = (const float*)d_in[1];
    const float* fc_in_w  = (const float*)d_in[2];
    const float* fc_in_b  = (const float*)d_in[3];
    const float* fc_proj_w= (const float*)d_in[4];
    const float* fc_proj_b= (const float*)d_in[5];
    const float* Wx       = (const float*)d_in[6];
    const float* Wh       = (const float*)d_in[7];
    const float* b0       = (const float*)d_in[8];
    const float* Wxh      = (const float*)d_in[9];
    const float* Whh      = (const float*)d_in[10];
    const float* bhy      = (const float*)d_in[11];
    const float* Wzx      = (const float*)d_in[12];
    const float* bzx      = (const float*)d_in[13];
    const float* Wzh      = (const float*)d_in[14];
    const float* bzh      = (const float*)d_in[15];
    const float* Wzb      = (const float*)d_in[16];
    const float* Dx       = (const float*)d_in[17];
    const float* Dh       = (const float*)d_in[18];
    const float* Db       = (const float*)d_in[19];
    float* out = (float*)d_out;

    k_transpose<<<(NSEQ * B * IND + 255) / 256, 256>>>(strokes);
    k_init<<<(B * 2560 + 255) / 256, 256>>>(z, fc_in_w, fc_in_b);
    k_pre_ax<<<dim3(64, NSEQ), 256>>>(Wx);
    k_pre_gxh<<<dim3(16, NSEQ), 256>>>(Wxh);
    k_pre_E<<<dim3(16, HY, 3), 256>>>(Wzx, Wzh, Wzb, Dx, Dh, Db);
    k_pre_Eb<<<32, 256>>>(bzx, bzh, Dx, Dh);

    k_seq<<<GRID, 256>>>(Wxh, Whh, bhy, Wh, b0);

    dim3 pg(2, NSEQ);
    k_proj<<<pg, 256>>>(fc_proj_w, fc_proj_b);
    k_mdn<<<(NSEQ * B * 21 + 255) / 256, 256>>>(out);
}